// round 1
// baseline (speedup 1.0000x reference)
#include <cuda_runtime.h>
#include <math.h>
#include <float.h>

#define NN 20000
#define EE 320000
#define EPSV 1e-16f

// ---------------- device scratch (static allocation; no cudaMalloc) -------
__device__ float g_QKVS1[NN * 512];   // per node: [q(128) | k(128) | v(128) | s(128)]
__device__ float g_H1[NN * 128];      // layer-1 output after relu
__device__ float g_sc1[EE * 4];       // scores then exp values
__device__ float g_m1[NN * 4];
__device__ float g_s1[NN * 4];
__device__ float g_AGG1[NN * 128];
__device__ float g_QKVS2[NN * 16];    // per node: [q(4) | k(4) | v(4) | s(4)]
__device__ float g_sc2[EE * 4];
__device__ float g_m2[NN * 4];
__device__ float g_s2[NN * 4];
__device__ float g_AGG2[NN * 4];
__device__ float g_accum;

// ---------------- helpers -------------------------------------------------
__device__ __forceinline__ void atomicMaxFloat(float* addr, float val) {
    // Ordered-int trick; handles negatives and -0.0 via signbit branch.
    if (__float_as_int(val) >= 0) {
        atomicMax((int*)addr, __float_as_int(val));
    } else {
        atomicMin((unsigned int*)addr, __float_as_uint(val));
    }
}

__device__ __forceinline__ void redAddV4(float* p, float a, float b, float c, float d) {
    asm volatile("red.global.add.v4.f32 [%0], {%1, %2, %3, %4};"
                 :: "l"(p), "f"(a), "f"(b), "f"(c), "f"(d) : "memory");
}

// ---------------- init ----------------------------------------------------
__global__ void init_kernel() {
    int i = blockIdx.x * blockDim.x + threadIdx.x;
    if (i < NN * 128) g_AGG1[i] = 0.0f;
    if (i < NN * 4) {
        g_m1[i] = -FLT_MAX; g_s1[i] = 0.0f;
        g_m2[i] = -FLT_MAX; g_s2[i] = 0.0f;
        g_AGG2[i] = 0.0f;
    }
    if (i == 0) g_accum = 0.0f;
}

// ---------------- layer-1 fused QKVS GEMM ---------------------------------
// x[N,128] @ Wm[128,128] + bm -> g_QKVS1[N, m*128 + col]
// BM=64, BN=64, BK=16, 256 threads, 4x4 micro-tile per thread.
__global__ void gemm1_kernel(const float* __restrict__ x,
                             const float* __restrict__ Wq, const float* __restrict__ bq,
                             const float* __restrict__ Wk, const float* __restrict__ bk,
                             const float* __restrict__ Wv, const float* __restrict__ bv,
                             const float* __restrict__ Ws, const float* __restrict__ bs) {
    __shared__ float As[16][68];  // [k][row] transposed, padded
    __shared__ float Bs[16][68];  // [k][col], padded

    int tid = threadIdx.x;
    int tx = tid & 15;           // 0..15 -> 4 cols each
    int ty = tid >> 4;           // 0..15 -> 4 rows each
    int row0 = blockIdx.x * 64;
    int m    = blockIdx.y >> 1;          // which weight matrix
    int col0 = (blockIdx.y & 1) * 64;    // column offset within that matrix

    const float* W = (m == 0) ? Wq : (m == 1) ? Wk : (m == 2) ? Wv : Ws;
    const float* B = (m == 0) ? bq : (m == 1) ? bk : (m == 2) ? bv : bs;

    float acc[4][4];
#pragma unroll
    for (int i = 0; i < 4; i++)
#pragma unroll
        for (int j = 0; j < 4; j++) acc[i][j] = 0.0f;

    int ka = tid & 15;            // As load: k index
    int ra = (tid >> 4) * 4;      // As load: 4 rows
    int jb = (tid & 15) * 4;      // Bs load: 4 cols
    int kb = tid >> 4;            // Bs load: k index

    for (int kt = 0; kt < 8; kt++) {
        int k0 = kt * 16;
#pragma unroll
        for (int i = 0; i < 4; i++) {
            int gr = row0 + ra + i;
            As[ka][ra + i] = (gr < NN) ? x[gr * 128 + k0 + ka] : 0.0f;
        }
        *(float4*)&Bs[kb][jb] = *(const float4*)&W[(k0 + kb) * 128 + col0 + jb];
        __syncthreads();

#pragma unroll
        for (int kk = 0; kk < 16; kk++) {
            float4 a = *(float4*)&As[kk][ty * 4];
            float4 b = *(float4*)&Bs[kk][tx * 4];
            acc[0][0] += a.x * b.x; acc[0][1] += a.x * b.y; acc[0][2] += a.x * b.z; acc[0][3] += a.x * b.w;
            acc[1][0] += a.y * b.x; acc[1][1] += a.y * b.y; acc[1][2] += a.y * b.z; acc[1][3] += a.y * b.w;
            acc[2][0] += a.z * b.x; acc[2][1] += a.z * b.y; acc[2][2] += a.z * b.z; acc[2][3] += a.z * b.w;
            acc[3][0] += a.w * b.x; acc[3][1] += a.w * b.y; acc[3][2] += a.w * b.z; acc[3][3] += a.w * b.w;
        }
        __syncthreads();
    }

    float4 bv4 = *(const float4*)&B[col0 + tx * 4];
#pragma unroll
    for (int i = 0; i < 4; i++) {
        int gr = row0 + ty * 4 + i;
        if (gr < NN) {
            float4 o;
            o.x = acc[i][0] + bv4.x;
            o.y = acc[i][1] + bv4.y;
            o.z = acc[i][2] + bv4.z;
            o.w = acc[i][3] + bv4.w;
            *(float4*)&g_QKVS1[gr * 512 + m * 128 + col0 + tx * 4] = o;
        }
    }
}

// ---------------- layer-1 scores + segment max ----------------------------
// one warp per edge; lane handles 4 channels; heads are 8-lane segments
__global__ void scores1_kernel(const int* __restrict__ src, const int* __restrict__ dst) {
    int gid = blockIdx.x * blockDim.x + threadIdx.x;
    int e = gid >> 5;
    int lane = gid & 31;
    if (e >= EE) return;
    int d = dst[e], s = src[e];
    float4 q = *(const float4*)&g_QKVS1[d * 512 + lane * 4];
    float4 k = *(const float4*)&g_QKVS1[s * 512 + 128 + lane * 4];
    float p = q.x * k.x + q.y * k.y + q.z * k.z + q.w * k.w;
    p += __shfl_down_sync(0xffffffffu, p, 4, 8);
    p += __shfl_down_sync(0xffffffffu, p, 2, 8);
    p += __shfl_down_sync(0xffffffffu, p, 1, 8);
    if ((lane & 7) == 0) {
        int h = lane >> 3;
        float sc = p * 0.17677669529663687f;  // 1/sqrt(32)
        g_sc1[e * 4 + h] = sc;
        atomicMaxFloat(&g_m1[d * 4 + h], sc);
    }
}

// ---------------- layer-1 exp + segment sum -------------------------------
__global__ void expsum1_kernel(const int* __restrict__ dst) {
    int i = blockIdx.x * blockDim.x + threadIdx.x;
    if (i >= EE * 4) return;
    int e = i >> 2, h = i & 3;
    int d = dst[e];
    float ev = expf(g_sc1[i] - g_m1[d * 4 + h]);
    g_sc1[i] = ev;
    atomicAdd(&g_s1[d * 4 + h], ev);
}

// ---------------- layer-1 weighted aggregation ----------------------------
__global__ void agg1_kernel(const int* __restrict__ src, const int* __restrict__ dst) {
    int gid = blockIdx.x * blockDim.x + threadIdx.x;
    int e = gid >> 5;
    int lane = gid & 31;
    if (e >= EE) return;
    int d = dst[e], s = src[e];
    int h = lane >> 3;
    float a = g_sc1[e * 4 + h] / (g_s1[d * 4 + h] + EPSV);
    float4 v = *(const float4*)&g_QKVS1[s * 512 + 256 + lane * 4];
    redAddV4(&g_AGG1[d * 128 + lane * 4], a * v.x, a * v.y, a * v.z, a * v.w);
}

// ---------------- layer-1 skip + relu -------------------------------------
__global__ void relu_kernel() {
    int i = blockIdx.x * blockDim.x + threadIdx.x;
    if (i >= NN * 128) return;
    int n = i >> 7, c = i & 127;
    float val = g_AGG1[i] + g_QKVS1[n * 512 + 384 + c];
    g_H1[i] = fmaxf(val, 0.0f);
}

// ---------------- layer-2 QKVS GEMM (tiny: 128 -> 4 per matrix) -----------
__global__ void gemm2_kernel(const float* __restrict__ Wq, const float* __restrict__ bq,
                             const float* __restrict__ Wk, const float* __restrict__ bk,
                             const float* __restrict__ Wv, const float* __restrict__ bv,
                             const float* __restrict__ Ws, const float* __restrict__ bs) {
    int gid = blockIdx.x * blockDim.x + threadIdx.x;
    if (gid >= NN * 16) return;
    int n = gid >> 4, j = gid & 15;
    int m = j >> 2, c = j & 3;
    const float* W = (m == 0) ? Wq : (m == 1) ? Wk : (m == 2) ? Wv : Ws;
    const float* B = (m == 0) ? bq : (m == 1) ? bk : (m == 2) ? bv : bs;
    float acc = B[c];
    const float* hrow = &g_H1[n * 128];
#pragma unroll 8
    for (int i = 0; i < 128; i++) acc += hrow[i] * W[i * 4 + c];
    g_QKVS2[gid] = acc;
}

// ---------------- layer-2 edge phase --------------------------------------
__global__ void scores2_kernel(const int* __restrict__ src, const int* __restrict__ dst) {
    int i = blockIdx.x * blockDim.x + threadIdx.x;
    if (i >= EE * 4) return;
    int e = i >> 2, h = i & 3;
    int d = dst[e], s = src[e];
    float sc = g_QKVS2[d * 16 + h] * g_QKVS2[s * 16 + 4 + h];  // ch=1, scale 1/sqrt(1)=1
    g_sc2[i] = sc;
    atomicMaxFloat(&g_m2[d * 4 + h], sc);
}

__global__ void expsum2_kernel(const int* __restrict__ dst) {
    int i = blockIdx.x * blockDim.x + threadIdx.x;
    if (i >= EE * 4) return;
    int e = i >> 2, h = i & 3;
    int d = dst[e];
    float ev = expf(g_sc2[i] - g_m2[d * 4 + h]);
    g_sc2[i] = ev;
    atomicAdd(&g_s2[d * 4 + h], ev);
}

__global__ void agg2_kernel(const int* __restrict__ src, const int* __restrict__ dst) {
    int i = blockIdx.x * blockDim.x + threadIdx.x;
    if (i >= EE * 4) return;
    int e = i >> 2, h = i & 3;
    int d = dst[e], s = src[e];
    float a = g_sc2[i] / (g_s2[d * 4 + h] + EPSV);
    atomicAdd(&g_AGG2[d * 4 + h], a * g_QKVS2[s * 16 + 8 + h]);
}

// ---------------- final linear + mean -------------------------------------
__global__ void final_kernel(const float* __restrict__ Wl) {
    int n = blockIdx.x * blockDim.x + threadIdx.x;
    float y = 0.0f;
    if (n < NN) {
#pragma unroll
        for (int h = 0; h < 4; h++)
            y += (g_AGG2[n * 4 + h] + g_QKVS2[n * 16 + 12 + h]) * Wl[h];
    }
    __shared__ float sh[256];
    sh[threadIdx.x] = y;
    __syncthreads();
    for (int s = 128; s > 0; s >>= 1) {
        if (threadIdx.x < s) sh[threadIdx.x] += sh[threadIdx.x + s];
        __syncthreads();
    }
    if (threadIdx.x == 0) atomicAdd(&g_accum, sh[0]);
}

__global__ void out_kernel(const float* __restrict__ bl, float* __restrict__ out) {
    out[0] = g_accum / (float)NN + bl[0];
}

// ---------------- launch --------------------------------------------------
extern "C" void kernel_launch(void* const* d_in, const int* in_sizes, int n_in,
                              void* d_out, int out_size) {
    const float* x    = (const float*)d_in[0];
    const int*   esrc = (const int*)d_in[1];
    const int*   edst = (const int*)d_in[2];
    const float* W1q = (const float*)d_in[3];  const float* b1q = (const float*)d_in[4];
    const float* W1k = (const float*)d_in[5];  const float* b1k = (const float*)d_in[6];
    const float* W1v = (const float*)d_in[7];  const float* b1v = (const float*)d_in[8];
    const float* W1s = (const float*)d_in[9];  const float* b1s = (const float*)d_in[10];
    const float* W2q = (const float*)d_in[11]; const float* b2q = (const float*)d_in[12];
    const float* W2k = (const float*)d_in[13]; const float* b2k = (const float*)d_in[14];
    const float* W2v = (const float*)d_in[15]; const float* b2v = (const float*)d_in[16];
    const float* W2s = (const float*)d_in[17]; const float* b2s = (const float*)d_in[18];
    const float* Wl  = (const float*)d_in[19]; const float* bl  = (const float*)d_in[20];
    float* out = (float*)d_out;

    init_kernel<<<(NN * 128 + 255) / 256, 256>>>();

    dim3 g1((NN + 63) / 64, 8);
    gemm1_kernel<<<g1, 256>>>(x, W1q, b1q, W1k, b1k, W1v, b1v, W1s, b1s);

    scores1_kernel<<<EE * 32 / 256, 256>>>(esrc, edst);
    expsum1_kernel<<<EE * 4 / 256, 256>>>(edst);
    agg1_kernel<<<EE * 32 / 256, 256>>>(esrc, edst);
    relu_kernel<<<NN * 128 / 256, 256>>>();

    gemm2_kernel<<<(NN * 16 + 255) / 256, 256>>>(W2q, b2q, W2k, b2k, W2v, b2v, W2s, b2s);

    scores2_kernel<<<EE * 4 / 256, 256>>>(esrc, edst);
    expsum2_kernel<<<EE * 4 / 256, 256>>>(edst);
    agg2_kernel<<<EE * 4 / 256, 256>>>(esrc, edst);

    final_kernel<<<(NN + 255) / 256, 256>>>(Wl);
    out_kernel<<<1, 1>>>(bl, out);
}

// round 3
// speedup vs baseline: 1.0480x; 1.0480x over previous
#include <cuda_runtime.h>
#include <math.h>
#include <float.h>

#define NN 20000
#define EE 320000
#define EPSV 1e-16f
#define SCALE1 0.17677669529663687f   // 1/sqrt(32)
#define DEG_CAP 256

// ---------------- device scratch (static; no cudaMalloc) ------------------
__device__ float g_QKVS1[NN * 512];   // per node: [q(128)|k(128)|v(128)|s(128)]
__device__ float g_QKVS2[NN * 16];    // per node: [q(4)|k(4)|v(4)|s(4)]
__device__ float g_sc1[EE * 4];       // score spill (only deg>DEG_CAP fallback)
__device__ int   g_deg[NN];
__device__ int   g_off[NN + 1];
__device__ int   g_pos[NN];
__device__ int   g_ssrc[EE];          // src sorted by dst (CSR payload)
__device__ float g_accum;

// ---------------- f32x2 packed-FMA helpers --------------------------------
#define FMA2(d, a, b, c) \
    asm("fma.rn.f32x2 %0, %1, %2, %3;" : "=l"(d) : "l"(a), "l"(b), "l"(c))
#define PACK2(o, lo, hi) \
    asm("mov.b64 %0, {%1, %2};" : "=l"(o) : "r"(lo), "r"(hi))
#define UNPACK2(lo, hi, in) \
    asm("mov.b64 {%0, %1}, %2;" : "=r"(lo), "=r"(hi) : "l"(in))

__device__ __forceinline__ unsigned fu(float x) { return __float_as_uint(x); }

// ---------------- init ----------------------------------------------------
__global__ void init_kernel() {
    int i = blockIdx.x * blockDim.x + threadIdx.x;
    if (i < NN) g_deg[i] = 0;
    if (i == 0) g_accum = 0.0f;
}

// ---------------- CSR build -----------------------------------------------
__global__ void hist_kernel(const int* __restrict__ dst) {
    int e = blockIdx.x * blockDim.x + threadIdx.x;
    if (e < EE) atomicAdd(&g_deg[dst[e]], 1);
}

// single-block exclusive scan over g_deg -> g_off, g_pos (warp-shfl based)
__global__ void scan_kernel() {
    __shared__ int wsum[32];
    __shared__ int carry_sh;
    int tid = threadIdx.x;
    int lane = tid & 31, wid = tid >> 5;
    if (tid == 0) { carry_sh = 0; g_off[0] = 0; }
    __syncthreads();

    const int CHUNKS = (NN + 1023) / 1024;
    for (int c = 0; c < CHUNKS; c++) {
        int i = c * 1024 + tid;
        int v = (i < NN) ? g_deg[i] : 0;
        int base = carry_sh;
        // warp inclusive scan
        int incl = v;
#pragma unroll
        for (int d = 1; d < 32; d <<= 1) {
            int t = __shfl_up_sync(0xffffffffu, incl, d);
            if (lane >= d) incl += t;
        }
        if (lane == 31) wsum[wid] = incl;
        __syncthreads();
        if (wid == 0) {
            int w = wsum[lane];
            int wi = w;
#pragma unroll
            for (int d = 1; d < 32; d <<= 1) {
                int t = __shfl_up_sync(0xffffffffu, wi, d);
                if (lane >= d) wi += t;
            }
            wsum[lane] = wi;  // inclusive across warps
        }
        __syncthreads();
        int wexcl = (wid == 0) ? 0 : wsum[wid - 1];
        int total = wsum[31];
        int my_incl = base + wexcl + incl;
        if (i < NN) {
            g_off[i + 1] = my_incl;
            g_pos[i] = my_incl - v;
        }
        __syncthreads();
        if (tid == 0) carry_sh = base + total;
        __syncthreads();
    }
}

__global__ void scatter_kernel(const int* __restrict__ src, const int* __restrict__ dst) {
    int e = blockIdx.x * blockDim.x + threadIdx.x;
    if (e >= EE) return;
    int p = atomicAdd(&g_pos[dst[e]], 1);
    g_ssrc[p] = src[e];
}

// ---------------- layer-1 fused QKVS GEMM (f32x2 packed) ------------------
// x[N,128] @ Wm[128,128] + bm  ->  g_QKVS1[N, m*128 + col]
// BM=64, BN=128 (full matrix), BK=16; 256 threads; 4x8 micro-tile.
__global__ void gemm1_kernel(const float* __restrict__ x,
                             const float* __restrict__ Wq, const float* __restrict__ bq,
                             const float* __restrict__ Wk, const float* __restrict__ bk,
                             const float* __restrict__ Wv, const float* __restrict__ bv,
                             const float* __restrict__ Ws, const float* __restrict__ bs) {
    __shared__ float As[16][64];    // [k][row]
    __shared__ float Bs[16][128];   // [k][col]

    int tid = threadIdx.x;
    int tx = tid & 15;     // col group: 8 cols each
    int ty = tid >> 4;     // row group: 4 rows each
    int row0 = blockIdx.x * 64;
    int m = blockIdx.y;

    const float* W = (m == 0) ? Wq : (m == 1) ? Wk : (m == 2) ? Wv : Ws;
    const float* B = (m == 0) ? bq : (m == 1) ? bk : (m == 2) ? bv : bs;

    unsigned long long acc[4][4];
#pragma unroll
    for (int i = 0; i < 4; i++)
#pragma unroll
        for (int j = 0; j < 4; j++) acc[i][j] = 0ull;

    int lrow = tid & 63;   // As load row
    int lkq  = tid >> 6;   // 0..3: k quad
    int bcol = (tid & 31) * 4;
    int bkk  = tid >> 5;   // 0..7

    for (int kt = 0; kt < 8; kt++) {
        int k0 = kt * 16;
        int gr = row0 + lrow;
        float4 xa = make_float4(0.f, 0.f, 0.f, 0.f);
        if (gr < NN) xa = *(const float4*)&x[gr * 128 + k0 + lkq * 4];
        As[lkq * 4 + 0][lrow] = xa.x;
        As[lkq * 4 + 1][lrow] = xa.y;
        As[lkq * 4 + 2][lrow] = xa.z;
        As[lkq * 4 + 3][lrow] = xa.w;
        *(float4*)&Bs[bkk][bcol]     = *(const float4*)&W[(k0 + bkk) * 128 + bcol];
        *(float4*)&Bs[bkk + 8][bcol] = *(const float4*)&W[(k0 + bkk + 8) * 128 + bcol];
        __syncthreads();

#pragma unroll
        for (int kk = 0; kk < 16; kk++) {
            float4 a  = *(float4*)&As[kk][ty * 4];
            float4 b0 = *(float4*)&Bs[kk][tx * 8];
            float4 b1 = *(float4*)&Bs[kk][tx * 8 + 4];
            unsigned long long bp0, bp1, bp2, bp3, ar;
            PACK2(bp0, fu(b0.x), fu(b0.y));
            PACK2(bp1, fu(b0.z), fu(b0.w));
            PACK2(bp2, fu(b1.x), fu(b1.y));
            PACK2(bp3, fu(b1.z), fu(b1.w));
            PACK2(ar, fu(a.x), fu(a.x));
            FMA2(acc[0][0], ar, bp0, acc[0][0]);
            FMA2(acc[0][1], ar, bp1, acc[0][1]);
            FMA2(acc[0][2], ar, bp2, acc[0][2]);
            FMA2(acc[0][3], ar, bp3, acc[0][3]);
            PACK2(ar, fu(a.y), fu(a.y));
            FMA2(acc[1][0], ar, bp0, acc[1][0]);
            FMA2(acc[1][1], ar, bp1, acc[1][1]);
            FMA2(acc[1][2], ar, bp2, acc[1][2]);
            FMA2(acc[1][3], ar, bp3, acc[1][3]);
            PACK2(ar, fu(a.z), fu(a.z));
            FMA2(acc[2][0], ar, bp0, acc[2][0]);
            FMA2(acc[2][1], ar, bp1, acc[2][1]);
            FMA2(acc[2][2], ar, bp2, acc[2][2]);
            FMA2(acc[2][3], ar, bp3, acc[2][3]);
            PACK2(ar, fu(a.w), fu(a.w));
            FMA2(acc[3][0], ar, bp0, acc[3][0]);
            FMA2(acc[3][1], ar, bp1, acc[3][1]);
            FMA2(acc[3][2], ar, bp2, acc[3][2]);
            FMA2(acc[3][3], ar, bp3, acc[3][3]);
        }
        __syncthreads();
    }

    float4 bb0 = *(const float4*)&B[tx * 8];
    float4 bb1 = *(const float4*)&B[tx * 8 + 4];
#pragma unroll
    for (int i = 0; i < 4; i++) {
        int gr = row0 + ty * 4 + i;
        if (gr < NN) {
            unsigned r0, r1;
            float4 o0, o1;
            UNPACK2(r0, r1, acc[i][0]);
            o0.x = __uint_as_float(r0) + bb0.x; o0.y = __uint_as_float(r1) + bb0.y;
            UNPACK2(r0, r1, acc[i][1]);
            o0.z = __uint_as_float(r0) + bb0.z; o0.w = __uint_as_float(r1) + bb0.w;
            UNPACK2(r0, r1, acc[i][2]);
            o1.x = __uint_as_float(r0) + bb1.x; o1.y = __uint_as_float(r1) + bb1.y;
            UNPACK2(r0, r1, acc[i][3]);
            o1.z = __uint_as_float(r0) + bb1.z; o1.w = __uint_as_float(r1) + bb1.w;
            *(float4*)&g_QKVS1[gr * 512 + m * 128 + tx * 8]     = o0;
            *(float4*)&g_QKVS1[gr * 512 + m * 128 + tx * 8 + 4] = o1;
        }
    }
}

// ---------------- layer-1 fused edge phase + gemm2 ------------------------
// warp per dst node: scores -> softmax -> aggregate -> skip+relu -> QKVS2
__global__ void edge1_fused(const float* __restrict__ W2q, const float* __restrict__ b2q,
                            const float* __restrict__ W2k, const float* __restrict__ b2k,
                            const float* __restrict__ W2v, const float* __restrict__ b2v,
                            const float* __restrict__ W2s, const float* __restrict__ b2s) {
    __shared__ float scs[8][DEG_CAP * 4];
    __shared__ float Wsm[16][128];    // [out j][in i], j = m*4+c
    __shared__ float bsm[16];

    int tid = threadIdx.x;
    // stage W2 (all 4 matrices as one [16][128]) into smem
    for (int f = tid; f < 2048; f += 256) {
        int j = f >> 7, i = f & 127;
        int mm = j >> 2, c = j & 3;
        const float* Wm = (mm == 0) ? W2q : (mm == 1) ? W2k : (mm == 2) ? W2v : W2s;
        Wsm[j][i] = Wm[i * 4 + c];
    }
    if (tid < 16) {
        int mm = tid >> 2, c = tid & 3;
        const float* bm = (mm == 0) ? b2q : (mm == 1) ? b2k : (mm == 2) ? b2v : b2s;
        bsm[tid] = bm[c];
    }
    __syncthreads();

    int wid = tid >> 5, lane = tid & 31;
    int n = blockIdx.x * 8 + wid;         // 2500*8 = 20000 exactly
    int h = lane >> 3;

    int off = g_off[n], end = g_off[n + 1];
    int deg = end - off;
    float* scp = (deg <= DEG_CAP) ? &scs[wid][0] : &g_sc1[(size_t)off * 4];

    float4 q = *(const float4*)&g_QKVS1[n * 512 + lane * 4];
    float mmax = -FLT_MAX;

    for (int i = 0; i < deg; i++) {
        int s = g_ssrc[off + i];
        float4 k = *(const float4*)&g_QKVS1[s * 512 + 128 + lane * 4];
        float p = q.x * k.x + q.y * k.y + q.z * k.z + q.w * k.w;
        p += __shfl_down_sync(0xffffffffu, p, 4, 8);
        p += __shfl_down_sync(0xffffffffu, p, 2, 8);
        p += __shfl_down_sync(0xffffffffu, p, 1, 8);
        // each lane learns its own head's score (head = lane>>3, base lane = lane&24)
        float sc = __shfl_sync(0xffffffffu, p, lane & 24) * SCALE1;
        mmax = fmaxf(mmax, sc);
        // lanes 0..3 write heads 0..3: head h's score lives at lane h*8
        float scw = __shfl_sync(0xffffffffu, p, (lane & 3) * 8) * SCALE1;
        if (lane < 4) scp[i * 4 + lane] = scw;
    }
    __syncwarp();

    float sum = 0.0f;
    float4 acc = make_float4(0.f, 0.f, 0.f, 0.f);
    for (int i = 0; i < deg; i++) {
        float e = __expf(scp[i * 4 + h] - mmax);
        sum += e;
        int s = g_ssrc[off + i];
        float4 v = *(const float4*)&g_QKVS1[s * 512 + 256 + lane * 4];
        acc.x += e * v.x; acc.y += e * v.y; acc.z += e * v.z; acc.w += e * v.w;
    }
    float inv = 1.0f / (sum + EPSV);
    float4 sk = *(const float4*)&g_QKVS1[n * 512 + 384 + lane * 4];
    float4 h1;
    h1.x = fmaxf(acc.x * inv + sk.x, 0.0f);
    h1.y = fmaxf(acc.y * inv + sk.y, 0.0f);
    h1.z = fmaxf(acc.z * inv + sk.z, 0.0f);
    h1.w = fmaxf(acc.w * inv + sk.w, 0.0f);

    // gemm2: 16 outputs per node, reduce across warp
    float part[16];
#pragma unroll
    for (int j = 0; j < 16; j++) {
        float4 w = *(float4*)&Wsm[j][lane * 4];
        part[j] = h1.x * w.x + h1.y * w.y + h1.z * w.z + h1.w * w.w;
#pragma unroll
        for (int s = 16; s > 0; s >>= 1)
            part[j] += __shfl_xor_sync(0xffffffffu, part[j], s);
    }
    if (lane == 0) {
        float4 o;
#pragma unroll
        for (int j4 = 0; j4 < 4; j4++) {
            o.x = part[j4 * 4 + 0] + bsm[j4 * 4 + 0];
            o.y = part[j4 * 4 + 1] + bsm[j4 * 4 + 1];
            o.z = part[j4 * 4 + 2] + bsm[j4 * 4 + 2];
            o.w = part[j4 * 4 + 3] + bsm[j4 * 4 + 3];
            *(float4*)&g_QKVS2[n * 16 + j4 * 4] = o;
        }
    }
}

// ---------------- layer-2 fused edge phase + final linear + mean ----------
__global__ void edge2_fused(const float* __restrict__ Wl) {
    __shared__ float ysm[8];
    int tid = threadIdx.x;
    int wid = tid >> 5, lane = tid & 31;
    int n = blockIdx.x * 8 + wid;

    int off = g_off[n], end = g_off[n + 1];
    float4 q = *(const float4*)&g_QKVS2[n * 16];

    float m0 = -FLT_MAX, m1 = -FLT_MAX, m2 = -FLT_MAX, m3 = -FLT_MAX;
    for (int idx = off + lane; idx < end; idx += 32) {
        int s = g_ssrc[idx];
        float4 k = *(const float4*)&g_QKVS2[s * 16 + 4];
        m0 = fmaxf(m0, q.x * k.x);
        m1 = fmaxf(m1, q.y * k.y);
        m2 = fmaxf(m2, q.z * k.z);
        m3 = fmaxf(m3, q.w * k.w);
    }
#pragma unroll
    for (int s = 16; s > 0; s >>= 1) {
        m0 = fmaxf(m0, __shfl_xor_sync(0xffffffffu, m0, s));
        m1 = fmaxf(m1, __shfl_xor_sync(0xffffffffu, m1, s));
        m2 = fmaxf(m2, __shfl_xor_sync(0xffffffffu, m2, s));
        m3 = fmaxf(m3, __shfl_xor_sync(0xffffffffu, m3, s));
    }

    float s0 = 0.f, s1 = 0.f, s2 = 0.f, s3 = 0.f;
    float a0 = 0.f, a1 = 0.f, a2 = 0.f, a3 = 0.f;
    for (int idx = off + lane; idx < end; idx += 32) {
        int s = g_ssrc[idx];
        float4 k = *(const float4*)&g_QKVS2[s * 16 + 4];
        float4 v = *(const float4*)&g_QKVS2[s * 16 + 8];
        float e0 = __expf(q.x * k.x - m0); s0 += e0; a0 += e0 * v.x;
        float e1 = __expf(q.y * k.y - m1); s1 += e1; a1 += e1 * v.y;
        float e2 = __expf(q.z * k.z - m2); s2 += e2; a2 += e2 * v.z;
        float e3 = __expf(q.w * k.w - m3); s3 += e3; a3 += e3 * v.w;
    }
#pragma unroll
    for (int s = 16; s > 0; s >>= 1) {
        s0 += __shfl_xor_sync(0xffffffffu, s0, s);
        s1 += __shfl_xor_sync(0xffffffffu, s1, s);
        s2 += __shfl_xor_sync(0xffffffffu, s2, s);
        s3 += __shfl_xor_sync(0xffffffffu, s3, s);
        a0 += __shfl_xor_sync(0xffffffffu, a0, s);
        a1 += __shfl_xor_sync(0xffffffffu, a1, s);
        a2 += __shfl_xor_sync(0xffffffffu, a2, s);
        a3 += __shfl_xor_sync(0xffffffffu, a3, s);
    }

    float y = 0.0f;
    if (lane == 0) {
        float4 sk = *(const float4*)&g_QKVS2[n * 16 + 12];
        float o0 = a0 / (s0 + EPSV) + sk.x;
        float o1 = a1 / (s1 + EPSV) + sk.y;
        float o2 = a2 / (s2 + EPSV) + sk.z;
        float o3 = a3 / (s3 + EPSV) + sk.w;
        y = o0 * Wl[0] + o1 * Wl[1] + o2 * Wl[2] + o3 * Wl[3];
        ysm[wid] = y;
    }
    __syncthreads();
    if (tid == 0) {
        float t = 0.f;
#pragma unroll
        for (int w = 0; w < 8; w++) t += ysm[w];
        atomicAdd(&g_accum, t);
    }
}

__global__ void out_kernel(const float* __restrict__ bl, float* __restrict__ out) {
    out[0] = g_accum * (1.0f / (float)NN) + bl[0];
}

// ---------------- launch --------------------------------------------------
extern "C" void kernel_launch(void* const* d_in, const int* in_sizes, int n_in,
                              void* d_out, int out_size) {
    const float* x    = (const float*)d_in[0];
    const int*   esrc = (const int*)d_in[1];
    const int*   edst = (const int*)d_in[2];
    const float* W1q = (const float*)d_in[3];  const float* b1q = (const float*)d_in[4];
    const float* W1k = (const float*)d_in[5];  const float* b1k = (const float*)d_in[6];
    const float* W1v = (const float*)d_in[7];  const float* b1v = (const float*)d_in[8];
    const float* W1s = (const float*)d_in[9];  const float* b1s = (const float*)d_in[10];
    const float* W2q = (const float*)d_in[11]; const float* b2q = (const float*)d_in[12];
    const float* W2k = (const float*)d_in[13]; const float* b2k = (const float*)d_in[14];
    const float* W2v = (const float*)d_in[15]; const float* b2v = (const float*)d_in[16];
    const float* W2s = (const float*)d_in[17]; const float* b2s = (const float*)d_in[18];
    const float* Wl  = (const float*)d_in[19]; const float* bl  = (const float*)d_in[20];
    float* out = (float*)d_out;

    init_kernel<<<(NN + 255) / 256, 256>>>();
    hist_kernel<<<(EE + 255) / 256, 256>>>(edst);
    scan_kernel<<<1, 1024>>>();
    scatter_kernel<<<(EE + 255) / 256, 256>>>(esrc, edst);

    dim3 g1((NN + 63) / 64, 4);
    gemm1_kernel<<<g1, 256>>>(x, W1q, b1q, W1k, b1k, W1v, b1v, W1s, b1s);

    edge1_fused<<<NN / 8, 256>>>(W2q, b2q, W2k, b2k, W2v, b2v, W2s, b2s);
    edge2_fused<<<NN / 8, 256>>>(Wl);
    out_kernel<<<1, 1>>>(bl, out);
}

// round 4
// speedup vs baseline: 1.2950x; 1.2357x over previous
#include <cuda_runtime.h>
#include <math.h>
#include <float.h>

#define NN 20000
#define EE 320000
#define EPSV 1e-16f
#define SCALE1 0.17677669529663687f   // 1/sqrt(32)
#define DEG_CAP 64

// ---------------- device scratch (static; no cudaMalloc) ------------------
__device__ float g_QKVS1[NN * 512];   // per node: [q(128)|k(128)|v(128)|s(128)]
__device__ float g_QKVS2[NN * 16];    // per node: [q(4)|k(4)|v(4)|s(4)]
__device__ float g_sc1[EE * 4];       // score spill (only deg>DEG_CAP fallback)
__device__ int   g_deg[NN];
__device__ int   g_off[NN + 1];
__device__ int   g_pos[NN];
__device__ int   g_ssrc[EE];          // src sorted by dst (CSR payload)
__device__ float g_accum;

// ---------------- f32x2 packed-FMA helpers --------------------------------
#define FMA2(d, a, b, c) \
    asm("fma.rn.f32x2 %0, %1, %2, %3;" : "=l"(d) : "l"(a), "l"(b), "l"(c))

__device__ __forceinline__ unsigned long long pack2(float lo, float hi) {
    unsigned long long o;
    asm("mov.b64 %0, {%1, %2};" : "=l"(o) : "r"(__float_as_uint(lo)), "r"(__float_as_uint(hi)));
    return o;
}
__device__ __forceinline__ float2 unpack2(unsigned long long v) {
    unsigned lo, hi;
    asm("mov.b64 {%0, %1}, %2;" : "=r"(lo), "=r"(hi) : "l"(v));
    return make_float2(__uint_as_float(lo), __uint_as_float(hi));
}
__device__ __forceinline__ float dot4(float4 a, float4 b) {
    return a.x * b.x + a.y * b.y + a.z * b.z + a.w * b.w;
}

// ---------------- init ----------------------------------------------------
__global__ void init_kernel() {
    int i = blockIdx.x * blockDim.x + threadIdx.x;
    if (i < NN) g_deg[i] = 0;
    if (i == 0) g_accum = 0.0f;
}

// ---------------- CSR build (4 edges/thread for MLP) ----------------------
__global__ void hist_kernel(const int* __restrict__ dst) {
    int t = blockIdx.x * blockDim.x + threadIdx.x;
    int e = t * 4;
    if (e < EE) {
        int4 d4 = *(const int4*)&dst[e];
        atomicAdd(&g_deg[d4.x], 1);
        atomicAdd(&g_deg[d4.y], 1);
        atomicAdd(&g_deg[d4.z], 1);
        atomicAdd(&g_deg[d4.w], 1);
    }
}

// single-block exclusive scan over g_deg -> g_off, g_pos
__global__ void scan_kernel() {
    __shared__ int wsum[32];
    __shared__ int carry_sh;
    int tid = threadIdx.x;
    int lane = tid & 31, wid = tid >> 5;
    if (tid == 0) { carry_sh = 0; g_off[0] = 0; }
    __syncthreads();

    const int CHUNKS = (NN + 1023) / 1024;
    for (int c = 0; c < CHUNKS; c++) {
        int i = c * 1024 + tid;
        int v = (i < NN) ? g_deg[i] : 0;
        int base = carry_sh;
        int incl = v;
#pragma unroll
        for (int d = 1; d < 32; d <<= 1) {
            int t = __shfl_up_sync(0xffffffffu, incl, d);
            if (lane >= d) incl += t;
        }
        if (lane == 31) wsum[wid] = incl;
        __syncthreads();
        if (wid == 0) {
            int wi = wsum[lane];
#pragma unroll
            for (int d = 1; d < 32; d <<= 1) {
                int t = __shfl_up_sync(0xffffffffu, wi, d);
                if (lane >= d) wi += t;
            }
            wsum[lane] = wi;
        }
        __syncthreads();
        int wexcl = (wid == 0) ? 0 : wsum[wid - 1];
        int total = wsum[31];
        int my_incl = base + wexcl + incl;
        if (i < NN) {
            g_off[i + 1] = my_incl;
            g_pos[i] = my_incl - v;
        }
        __syncthreads();
        if (tid == 0) carry_sh = base + total;
        __syncthreads();
    }
}

__global__ void scatter_kernel(const int* __restrict__ src, const int* __restrict__ dst) {
    int t = blockIdx.x * blockDim.x + threadIdx.x;
    int e = t * 4;
    if (e >= EE) return;
    int4 d4 = *(const int4*)&dst[e];
    int4 s4 = *(const int4*)&src[e];
    int p0 = atomicAdd(&g_pos[d4.x], 1);
    int p1 = atomicAdd(&g_pos[d4.y], 1);
    int p2 = atomicAdd(&g_pos[d4.z], 1);
    int p3 = atomicAdd(&g_pos[d4.w], 1);
    g_ssrc[p0] = s4.x;
    g_ssrc[p1] = s4.y;
    g_ssrc[p2] = s4.z;
    g_ssrc[p3] = s4.w;
}

// ---------------- layer-1 fused QKVS GEMM (f32x2, MOV-free inner loop) ----
// x[N,128] @ Wm[128,128] + bm -> g_QKVS1[N, m*128 + col]
// BM=128, BN=128, BK=16; 256 threads; 8x8 micro-tile.
__global__ __launch_bounds__(256) void gemm1_kernel(
        const float* __restrict__ x,
        const float* __restrict__ Wq, const float* __restrict__ bq,
        const float* __restrict__ Wk, const float* __restrict__ bk,
        const float* __restrict__ Wv, const float* __restrict__ bv,
        const float* __restrict__ Ws, const float* __restrict__ bs) {
    __shared__ unsigned long long As2[16][128];   // (a,a) packed, [k][row]
    __shared__ float Bs[16][128];                 // [k][col]

    int tid = threadIdx.x;
    int tx = tid & 15;     // col group: 8 cols
    int ty = tid >> 4;     // row group: 8 rows
    int row0 = blockIdx.x * 128;
    int m = blockIdx.y;

    const float* W = (m == 0) ? Wq : (m == 1) ? Wk : (m == 2) ? Wv : Ws;
    const float* B = (m == 0) ? bq : (m == 1) ? bk : (m == 2) ? bv : bs;

    unsigned long long acc[8][4];
#pragma unroll
    for (int i = 0; i < 8; i++)
#pragma unroll
        for (int j = 0; j < 4; j++) acc[i][j] = 0ull;

    int arow = tid & 127;        // A load: row
    int akq  = (tid >> 7) * 8;   // A load: k offset (0 or 8)
    int bcol = (tid & 31) * 4;   // B load: col
    int bkr  = tid >> 5;         // B load: k row (0..7)

    for (int kt = 0; kt < 8; kt++) {
        int k0 = kt * 16;
        int gr = row0 + arow;
        float4 xa = make_float4(0.f, 0.f, 0.f, 0.f);
        float4 xb = make_float4(0.f, 0.f, 0.f, 0.f);
        if (gr < NN) {
            xa = *(const float4*)&x[gr * 128 + k0 + akq];
            xb = *(const float4*)&x[gr * 128 + k0 + akq + 4];
        }
        As2[akq + 0][arow] = pack2(xa.x, xa.x);
        As2[akq + 1][arow] = pack2(xa.y, xa.y);
        As2[akq + 2][arow] = pack2(xa.z, xa.z);
        As2[akq + 3][arow] = pack2(xa.w, xa.w);
        As2[akq + 4][arow] = pack2(xb.x, xb.x);
        As2[akq + 5][arow] = pack2(xb.y, xb.y);
        As2[akq + 6][arow] = pack2(xb.z, xb.z);
        As2[akq + 7][arow] = pack2(xb.w, xb.w);
        *(float4*)&Bs[bkr][bcol]     = *(const float4*)&W[(k0 + bkr) * 128 + bcol];
        *(float4*)&Bs[bkr + 8][bcol] = *(const float4*)&W[(k0 + bkr + 8) * 128 + bcol];
        __syncthreads();

#pragma unroll
        for (int kk = 0; kk < 16; kk++) {
            ulonglong2 b01 = *(ulonglong2*)&Bs[kk][tx * 8];
            ulonglong2 b23 = *(ulonglong2*)&Bs[kk][tx * 8 + 4];
#pragma unroll
            for (int i = 0; i < 8; i++) {
                unsigned long long a = As2[kk][ty * 8 + i];
                FMA2(acc[i][0], a, b01.x, acc[i][0]);
                FMA2(acc[i][1], a, b01.y, acc[i][1]);
                FMA2(acc[i][2], a, b23.x, acc[i][2]);
                FMA2(acc[i][3], a, b23.y, acc[i][3]);
            }
        }
        __syncthreads();
    }

    float4 bb0 = *(const float4*)&B[tx * 8];
    float4 bb1 = *(const float4*)&B[tx * 8 + 4];
#pragma unroll
    for (int i = 0; i < 8; i++) {
        int gr = row0 + ty * 8 + i;
        if (gr < NN) {
            float2 p0 = unpack2(acc[i][0]);
            float2 p1 = unpack2(acc[i][1]);
            float2 p2 = unpack2(acc[i][2]);
            float2 p3 = unpack2(acc[i][3]);
            float4 o0 = make_float4(p0.x + bb0.x, p0.y + bb0.y, p1.x + bb0.z, p1.y + bb0.w);
            float4 o1 = make_float4(p2.x + bb1.x, p2.y + bb1.y, p3.x + bb1.z, p3.y + bb1.w);
            *(float4*)&g_QKVS1[gr * 512 + m * 128 + tx * 8]     = o0;
            *(float4*)&g_QKVS1[gr * 512 + m * 128 + tx * 8 + 4] = o1;
        }
    }
}

// ---------------- layer-1 fused edge phase + gemm2 ------------------------
// warp per dst node: scores -> softmax -> aggregate -> skip+relu -> QKVS2
__global__ void edge1_fused(const float* __restrict__ W2q, const float* __restrict__ b2q,
                            const float* __restrict__ W2k, const float* __restrict__ b2k,
                            const float* __restrict__ W2v, const float* __restrict__ b2v,
                            const float* __restrict__ W2s, const float* __restrict__ b2s) {
    __shared__ float scs[8][DEG_CAP * 4];
    __shared__ float Wsm[16][128];    // [out j][in i], j = m*4+c
    __shared__ float bsm[16];

    int tid = threadIdx.x;
    for (int f = tid; f < 2048; f += 256) {
        int j = f >> 7, i = f & 127;
        int mm = j >> 2, c = j & 3;
        const float* Wm = (mm == 0) ? W2q : (mm == 1) ? W2k : (mm == 2) ? W2v : W2s;
        Wsm[j][i] = Wm[i * 4 + c];
    }
    if (tid < 16) {
        int mm = tid >> 2, c = tid & 3;
        const float* bm = (mm == 0) ? b2q : (mm == 1) ? b2k : (mm == 2) ? b2v : b2s;
        bsm[tid] = bm[c];
    }
    __syncthreads();

    int wid = tid >> 5, lane = tid & 31;
    int n = blockIdx.x * 8 + wid;         // 2500*8 = 20000 exactly
    int h = lane >> 3;

    int off = g_off[n], end = g_off[n + 1];
    int deg = end - off;
    float* scp = (deg <= DEG_CAP) ? &scs[wid][0] : &g_sc1[(size_t)off * 4];
    bool writer = (lane & 7) == 0;

    float4 q = *(const float4*)&g_QKVS1[n * 512 + lane * 4];
    float mmax = -FLT_MAX;

    int i = 0;
    for (; i + 4 <= deg; i += 4) {
        int s0 = g_ssrc[off + i];
        int s1 = g_ssrc[off + i + 1];
        int s2 = g_ssrc[off + i + 2];
        int s3 = g_ssrc[off + i + 3];
        float4 k0 = *(const float4*)&g_QKVS1[s0 * 512 + 128 + lane * 4];
        float4 k1 = *(const float4*)&g_QKVS1[s1 * 512 + 128 + lane * 4];
        float4 k2 = *(const float4*)&g_QKVS1[s2 * 512 + 128 + lane * 4];
        float4 k3 = *(const float4*)&g_QKVS1[s3 * 512 + 128 + lane * 4];
        float p0 = dot4(q, k0), p1 = dot4(q, k1), p2 = dot4(q, k2), p3 = dot4(q, k3);
#pragma unroll
        for (int d = 4; d > 0; d >>= 1) {
            p0 += __shfl_xor_sync(0xffffffffu, p0, d, 8);
            p1 += __shfl_xor_sync(0xffffffffu, p1, d, 8);
            p2 += __shfl_xor_sync(0xffffffffu, p2, d, 8);
            p3 += __shfl_xor_sync(0xffffffffu, p3, d, 8);
        }
        p0 *= SCALE1; p1 *= SCALE1; p2 *= SCALE1; p3 *= SCALE1;
        mmax = fmaxf(fmaxf(mmax, fmaxf(p0, p1)), fmaxf(p2, p3));
        if (writer) {
            scp[(i + 0) * 4 + h] = p0;
            scp[(i + 1) * 4 + h] = p1;
            scp[(i + 2) * 4 + h] = p2;
            scp[(i + 3) * 4 + h] = p3;
        }
    }
    for (; i < deg; i++) {
        int s = g_ssrc[off + i];
        float4 k = *(const float4*)&g_QKVS1[s * 512 + 128 + lane * 4];
        float p = dot4(q, k);
#pragma unroll
        for (int d = 4; d > 0; d >>= 1) p += __shfl_xor_sync(0xffffffffu, p, d, 8);
        p *= SCALE1;
        mmax = fmaxf(mmax, p);
        if (writer) scp[i * 4 + h] = p;
    }
    __syncwarp();

    float sum = 0.0f;
    float4 acc = make_float4(0.f, 0.f, 0.f, 0.f);
    i = 0;
    for (; i + 4 <= deg; i += 4) {
        float e0 = __expf(scp[(i + 0) * 4 + h] - mmax);
        float e1 = __expf(scp[(i + 1) * 4 + h] - mmax);
        float e2 = __expf(scp[(i + 2) * 4 + h] - mmax);
        float e3 = __expf(scp[(i + 3) * 4 + h] - mmax);
        int s0 = g_ssrc[off + i];
        int s1 = g_ssrc[off + i + 1];
        int s2 = g_ssrc[off + i + 2];
        int s3 = g_ssrc[off + i + 3];
        float4 v0 = *(const float4*)&g_QKVS1[s0 * 512 + 256 + lane * 4];
        float4 v1 = *(const float4*)&g_QKVS1[s1 * 512 + 256 + lane * 4];
        float4 v2 = *(const float4*)&g_QKVS1[s2 * 512 + 256 + lane * 4];
        float4 v3 = *(const float4*)&g_QKVS1[s3 * 512 + 256 + lane * 4];
        sum += (e0 + e1) + (e2 + e3);
        acc.x += e0 * v0.x + e1 * v1.x + e2 * v2.x + e3 * v3.x;
        acc.y += e0 * v0.y + e1 * v1.y + e2 * v2.y + e3 * v3.y;
        acc.z += e0 * v0.z + e1 * v1.z + e2 * v2.z + e3 * v3.z;
        acc.w += e0 * v0.w + e1 * v1.w + e2 * v2.w + e3 * v3.w;
    }
    for (; i < deg; i++) {
        float e = __expf(scp[i * 4 + h] - mmax);
        sum += e;
        int s = g_ssrc[off + i];
        float4 v = *(const float4*)&g_QKVS1[s * 512 + 256 + lane * 4];
        acc.x += e * v.x; acc.y += e * v.y; acc.z += e * v.z; acc.w += e * v.w;
    }
    float inv = 1.0f / (sum + EPSV);
    float4 sk = *(const float4*)&g_QKVS1[n * 512 + 384 + lane * 4];
    float4 h1;
    h1.x = fmaxf(acc.x * inv + sk.x, 0.0f);
    h1.y = fmaxf(acc.y * inv + sk.y, 0.0f);
    h1.z = fmaxf(acc.z * inv + sk.z, 0.0f);
    h1.w = fmaxf(acc.w * inv + sk.w, 0.0f);

    // gemm2: 16 outputs per node, reduce across warp
    float part[16];
#pragma unroll
    for (int j = 0; j < 16; j++) {
        float4 w = *(float4*)&Wsm[j][lane * 4];
        part[j] = h1.x * w.x + h1.y * w.y + h1.z * w.z + h1.w * w.w;
#pragma unroll
        for (int s = 16; s > 0; s >>= 1)
            part[j] += __shfl_xor_sync(0xffffffffu, part[j], s);
    }
    if (lane == 0) {
        float4 o;
#pragma unroll
        for (int j4 = 0; j4 < 4; j4++) {
            o.x = part[j4 * 4 + 0] + bsm[j4 * 4 + 0];
            o.y = part[j4 * 4 + 1] + bsm[j4 * 4 + 1];
            o.z = part[j4 * 4 + 2] + bsm[j4 * 4 + 2];
            o.w = part[j4 * 4 + 3] + bsm[j4 * 4 + 3];
            *(float4*)&g_QKVS2[n * 16 + j4 * 4] = o;
        }
    }
}

// ---------------- layer-2 fused edge phase + final linear + mean ----------
__global__ void edge2_fused(const float* __restrict__ Wl) {
    __shared__ float ysm[8];
    int tid = threadIdx.x;
    int wid = tid >> 5, lane = tid & 31;
    int n = blockIdx.x * 8 + wid;

    int off = g_off[n], end = g_off[n + 1];
    float4 q = *(const float4*)&g_QKVS2[n * 16];

    float m0 = -FLT_MAX, m1 = -FLT_MAX, m2 = -FLT_MAX, m3 = -FLT_MAX;
    for (int idx = off + lane; idx < end; idx += 32) {
        int s = g_ssrc[idx];
        float4 k = *(const float4*)&g_QKVS2[s * 16 + 4];
        m0 = fmaxf(m0, q.x * k.x);
        m1 = fmaxf(m1, q.y * k.y);
        m2 = fmaxf(m2, q.z * k.z);
        m3 = fmaxf(m3, q.w * k.w);
    }
#pragma unroll
    for (int s = 16; s > 0; s >>= 1) {
        m0 = fmaxf(m0, __shfl_xor_sync(0xffffffffu, m0, s));
        m1 = fmaxf(m1, __shfl_xor_sync(0xffffffffu, m1, s));
        m2 = fmaxf(m2, __shfl_xor_sync(0xffffffffu, m2, s));
        m3 = fmaxf(m3, __shfl_xor_sync(0xffffffffu, m3, s));
    }

    float s0 = 0.f, s1 = 0.f, s2 = 0.f, s3 = 0.f;
    float a0 = 0.f, a1 = 0.f, a2 = 0.f, a3 = 0.f;
    for (int idx = off + lane; idx < end; idx += 32) {
        int s = g_ssrc[idx];
        float4 k = *(const float4*)&g_QKVS2[s * 16 + 4];
        float4 v = *(const float4*)&g_QKVS2[s * 16 + 8];
        float e0 = __expf(q.x * k.x - m0); s0 += e0; a0 += e0 * v.x;
        float e1 = __expf(q.y * k.y - m1); s1 += e1; a1 += e1 * v.y;
        float e2 = __expf(q.z * k.z - m2); s2 += e2; a2 += e2 * v.z;
        float e3 = __expf(q.w * k.w - m3); s3 += e3; a3 += e3 * v.w;
    }
#pragma unroll
    for (int s = 16; s > 0; s >>= 1) {
        s0 += __shfl_xor_sync(0xffffffffu, s0, s);
        s1 += __shfl_xor_sync(0xffffffffu, s1, s);
        s2 += __shfl_xor_sync(0xffffffffu, s2, s);
        s3 += __shfl_xor_sync(0xffffffffu, s3, s);
        a0 += __shfl_xor_sync(0xffffffffu, a0, s);
        a1 += __shfl_xor_sync(0xffffffffu, a1, s);
        a2 += __shfl_xor_sync(0xffffffffu, a2, s);
        a3 += __shfl_xor_sync(0xffffffffu, a3, s);
    }

    float y = 0.0f;
    if (lane == 0) {
        float4 sk = *(const float4*)&g_QKVS2[n * 16 + 12];
        float o0 = a0 / (s0 + EPSV) + sk.x;
        float o1 = a1 / (s1 + EPSV) + sk.y;
        float o2 = a2 / (s2 + EPSV) + sk.z;
        float o3 = a3 / (s3 + EPSV) + sk.w;
        y = o0 * Wl[0] + o1 * Wl[1] + o2 * Wl[2] + o3 * Wl[3];
        ysm[wid] = y;
    }
    __syncthreads();
    if (tid == 0) {
        float t = 0.f;
#pragma unroll
        for (int w = 0; w < 8; w++) t += ysm[w];
        atomicAdd(&g_accum, t);
    }
}

__global__ void out_kernel(const float* __restrict__ bl, float* __restrict__ out) {
    out[0] = g_accum * (1.0f / (float)NN) + bl[0];
}

// ---------------- launch --------------------------------------------------
extern "C" void kernel_launch(void* const* d_in, const int* in_sizes, int n_in,
                              void* d_out, int out_size) {
    const float* x    = (const float*)d_in[0];
    const int*   esrc = (const int*)d_in[1];
    const int*   edst = (const int*)d_in[2];
    const float* W1q = (const float*)d_in[3];  const float* b1q = (const float*)d_in[4];
    const float* W1k = (const float*)d_in[5];  const float* b1k = (const float*)d_in[6];
    const float* W1v = (const float*)d_in[7];  const float* b1v = (const float*)d_in[8];
    const float* W1s = (const float*)d_in[9];  const float* b1s = (const float*)d_in[10];
    const float* W2q = (const float*)d_in[11]; const float* b2q = (const float*)d_in[12];
    const float* W2k = (const float*)d_in[13]; const float* b2k = (const float*)d_in[14];
    const float* W2v = (const float*)d_in[15]; const float* b2v = (const float*)d_in[16];
    const float* W2s = (const float*)d_in[17]; const float* b2s = (const float*)d_in[18];
    const float* Wl  = (const float*)d_in[19]; const float* bl  = (const float*)d_in[20];
    float* out = (float*)d_out;

    init_kernel<<<(NN + 255) / 256, 256>>>();
    hist_kernel<<<(EE / 4 + 255) / 256, 256>>>(edst);
    scan_kernel<<<1, 1024>>>();
    scatter_kernel<<<(EE / 4 + 255) / 256, 256>>>(esrc, edst);

    dim3 g1((NN + 127) / 128, 4);
    gemm1_kernel<<<g1, 256>>>(x, W1q, b1q, W1k, b1k, W1v, b1v, W1s, b1s);

    edge1_fused<<<NN / 8, 256>>>(W2q, b2q, W2k, b2k, W2v, b2v, W2s, b2s);
    edge2_fused<<<NN / 8, 256>>>(Wl);
    out_kernel<<<1, 1>>>(bl, out);
}

// round 5
// speedup vs baseline: 1.3486x; 1.0413x over previous
#include <cuda_runtime.h>
#include <math.h>
#include <float.h>

#define NN 20000
#define EE 320000
#define EPSV 1e-16f
#define SCALE1 0.17677669529663687f   // 1/sqrt(32)

// ---------------- device scratch (static; no cudaMalloc) ------------------
__device__ float g_QKVS1[NN * 512];   // per node: [q(128)|k(128)|v(128)|s(128)]
__device__ float g_QKVS2[NN * 16];    // per node: [q(4)|kv interleaved(8)|s(4)]
__device__ int   g_deg[NN];
__device__ int   g_off[NN + 1];
__device__ int   g_pos[NN];
__device__ int   g_ssrc[EE];          // src sorted by dst (CSR payload)
__device__ float g_accum;
__device__ int   g_done;

// ---------------- f32x2 packed-FMA helpers --------------------------------
#define FMA2(d, a, b, c) \
    asm("fma.rn.f32x2 %0, %1, %2, %3;" : "=l"(d) : "l"(a), "l"(b), "l"(c))

__device__ __forceinline__ unsigned long long pack2(float lo, float hi) {
    unsigned long long o;
    asm("mov.b64 %0, {%1, %2};" : "=l"(o) : "r"(__float_as_uint(lo)), "r"(__float_as_uint(hi)));
    return o;
}
__device__ __forceinline__ float2 unpack2(unsigned long long v) {
    unsigned lo, hi;
    asm("mov.b64 {%0, %1}, %2;" : "=r"(lo), "=r"(hi) : "l"(v));
    return make_float2(__uint_as_float(lo), __uint_as_float(hi));
}
__device__ __forceinline__ float dot4(float4 a, float4 b) {
    return a.x * b.x + a.y * b.y + a.z * b.z + a.w * b.w;
}

// ---------------- init ----------------------------------------------------
__global__ void init_kernel() {
    int i = blockIdx.x * blockDim.x + threadIdx.x;
    if (i < NN) g_deg[i] = 0;
    if (i == 0) { g_accum = 0.0f; g_done = 0; }
}

// ---------------- CSR build (4 edges/thread for MLP) ----------------------
__global__ void hist_kernel(const int* __restrict__ dst) {
    int t = blockIdx.x * blockDim.x + threadIdx.x;
    int e = t * 4;
    if (e < EE) {
        int4 d4 = *(const int4*)&dst[e];
        atomicAdd(&g_deg[d4.x], 1);
        atomicAdd(&g_deg[d4.y], 1);
        atomicAdd(&g_deg[d4.z], 1);
        atomicAdd(&g_deg[d4.w], 1);
    }
}

// single-block exclusive scan over g_deg -> g_off, g_pos
__global__ void scan_kernel() {
    __shared__ int wsum[32];
    __shared__ int carry_sh;
    int tid = threadIdx.x;
    int lane = tid & 31, wid = tid >> 5;
    if (tid == 0) { carry_sh = 0; g_off[0] = 0; }
    __syncthreads();

    const int CHUNKS = (NN + 1023) / 1024;
    for (int c = 0; c < CHUNKS; c++) {
        int i = c * 1024 + tid;
        int v = (i < NN) ? g_deg[i] : 0;
        int base = carry_sh;
        int incl = v;
#pragma unroll
        for (int d = 1; d < 32; d <<= 1) {
            int t = __shfl_up_sync(0xffffffffu, incl, d);
            if (lane >= d) incl += t;
        }
        if (lane == 31) wsum[wid] = incl;
        __syncthreads();
        if (wid == 0) {
            int wi = wsum[lane];
#pragma unroll
            for (int d = 1; d < 32; d <<= 1) {
                int t = __shfl_up_sync(0xffffffffu, wi, d);
                if (lane >= d) wi += t;
            }
            wsum[lane] = wi;
        }
        __syncthreads();
        int wexcl = (wid == 0) ? 0 : wsum[wid - 1];
        int total = wsum[31];
        int my_incl = base + wexcl + incl;
        if (i < NN) {
            g_off[i + 1] = my_incl;
            g_pos[i] = my_incl - v;
        }
        __syncthreads();
        if (tid == 0) carry_sh = base + total;
        __syncthreads();
    }
}

__global__ void scatter_kernel(const int* __restrict__ src, const int* __restrict__ dst) {
    int t = blockIdx.x * blockDim.x + threadIdx.x;
    int e = t * 4;
    if (e >= EE) return;
    int4 d4 = *(const int4*)&dst[e];
    int4 s4 = *(const int4*)&src[e];
    int p0 = atomicAdd(&g_pos[d4.x], 1);
    int p1 = atomicAdd(&g_pos[d4.y], 1);
    int p2 = atomicAdd(&g_pos[d4.z], 1);
    int p3 = atomicAdd(&g_pos[d4.w], 1);
    g_ssrc[p0] = s4.x;
    g_ssrc[p1] = s4.y;
    g_ssrc[p2] = s4.z;
    g_ssrc[p3] = s4.w;
}

// ---------------- layer-1 fused QKVS GEMM (f32x2, MOV-free inner loop) ----
__global__ __launch_bounds__(256) void gemm1_kernel(
        const float* __restrict__ x,
        const float* __restrict__ Wq, const float* __restrict__ bq,
        const float* __restrict__ Wk, const float* __restrict__ bk,
        const float* __restrict__ Wv, const float* __restrict__ bv,
        const float* __restrict__ Ws, const float* __restrict__ bs) {
    __shared__ unsigned long long As2[16][128];   // (a,a) packed, [k][row]
    __shared__ float Bs[16][128];                 // [k][col]

    int tid = threadIdx.x;
    int tx = tid & 15;
    int ty = tid >> 4;
    int row0 = blockIdx.x * 128;
    int m = blockIdx.y;

    const float* W = (m == 0) ? Wq : (m == 1) ? Wk : (m == 2) ? Wv : Ws;
    const float* B = (m == 0) ? bq : (m == 1) ? bk : (m == 2) ? bv : bs;

    unsigned long long acc[8][4];
#pragma unroll
    for (int i = 0; i < 8; i++)
#pragma unroll
        for (int j = 0; j < 4; j++) acc[i][j] = 0ull;

    int arow = tid & 127;
    int akq  = (tid >> 7) * 8;
    int bcol = (tid & 31) * 4;
    int bkr  = tid >> 5;

    for (int kt = 0; kt < 8; kt++) {
        int k0 = kt * 16;
        int gr = row0 + arow;
        float4 xa = make_float4(0.f, 0.f, 0.f, 0.f);
        float4 xb = make_float4(0.f, 0.f, 0.f, 0.f);
        if (gr < NN) {
            xa = *(const float4*)&x[gr * 128 + k0 + akq];
            xb = *(const float4*)&x[gr * 128 + k0 + akq + 4];
        }
        As2[akq + 0][arow] = pack2(xa.x, xa.x);
        As2[akq + 1][arow] = pack2(xa.y, xa.y);
        As2[akq + 2][arow] = pack2(xa.z, xa.z);
        As2[akq + 3][arow] = pack2(xa.w, xa.w);
        As2[akq + 4][arow] = pack2(xb.x, xb.x);
        As2[akq + 5][arow] = pack2(xb.y, xb.y);
        As2[akq + 6][arow] = pack2(xb.z, xb.z);
        As2[akq + 7][arow] = pack2(xb.w, xb.w);
        *(float4*)&Bs[bkr][bcol]     = *(const float4*)&W[(k0 + bkr) * 128 + bcol];
        *(float4*)&Bs[bkr + 8][bcol] = *(const float4*)&W[(k0 + bkr + 8) * 128 + bcol];
        __syncthreads();

#pragma unroll
        for (int kk = 0; kk < 16; kk++) {
            ulonglong2 b01 = *(ulonglong2*)&Bs[kk][tx * 8];
            ulonglong2 b23 = *(ulonglong2*)&Bs[kk][tx * 8 + 4];
#pragma unroll
            for (int i = 0; i < 8; i++) {
                unsigned long long a = As2[kk][ty * 8 + i];
                FMA2(acc[i][0], a, b01.x, acc[i][0]);
                FMA2(acc[i][1], a, b01.y, acc[i][1]);
                FMA2(acc[i][2], a, b23.x, acc[i][2]);
                FMA2(acc[i][3], a, b23.y, acc[i][3]);
            }
        }
        __syncthreads();
    }

    float4 bb0 = *(const float4*)&B[tx * 8];
    float4 bb1 = *(const float4*)&B[tx * 8 + 4];
#pragma unroll
    for (int i = 0; i < 8; i++) {
        int gr = row0 + ty * 8 + i;
        if (gr < NN) {
            float2 p0 = unpack2(acc[i][0]);
            float2 p1 = unpack2(acc[i][1]);
            float2 p2 = unpack2(acc[i][2]);
            float2 p3 = unpack2(acc[i][3]);
            float4 o0 = make_float4(p0.x + bb0.x, p0.y + bb0.y, p1.x + bb0.z, p1.y + bb0.w);
            float4 o1 = make_float4(p2.x + bb1.x, p2.y + bb1.y, p3.x + bb1.z, p3.y + bb1.w);
            *(float4*)&g_QKVS1[gr * 512 + m * 128 + tx * 8]     = o0;
            *(float4*)&g_QKVS1[gr * 512 + m * 128 + tx * 8 + 4] = o1;
        }
    }
}

// ---------------- layer-1 fused edge phase + gemm2 (single pass) ----------
// warp per dst node, max-free softmax: one loop gathers k AND v per edge.
__global__ __launch_bounds__(256) void edge1_fused(
        const float* __restrict__ W2q, const float* __restrict__ b2q,
        const float* __restrict__ W2k, const float* __restrict__ b2k,
        const float* __restrict__ W2v, const float* __restrict__ b2v,
        const float* __restrict__ W2s, const float* __restrict__ b2s) {
    __shared__ float Wsm[16][128];    // [out j][in i], j = m*4+c
    __shared__ float bsm[16];

    int tid = threadIdx.x;
    for (int f = tid; f < 2048; f += 256) {
        int j = f >> 7, i = f & 127;
        int mm = j >> 2, c = j & 3;
        const float* Wm = (mm == 0) ? W2q : (mm == 1) ? W2k : (mm == 2) ? W2v : W2s;
        Wsm[j][i] = Wm[i * 4 + c];
    }
    if (tid < 16) {
        int mm = tid >> 2, c = tid & 3;
        const float* bm = (mm == 0) ? b2q : (mm == 1) ? b2k : (mm == 2) ? b2v : b2s;
        bsm[tid] = bm[c];
    }
    __syncthreads();

    int wid = tid >> 5, lane = tid & 31;
    int n = blockIdx.x * 8 + wid;         // 2500*8 = 20000 exactly

    int off = g_off[n], end = g_off[n + 1];
    int deg = end - off;

    float4 q = *(const float4*)&g_QKVS1[n * 512 + lane * 4];
    float sum = 0.0f;
    float4 acc = make_float4(0.f, 0.f, 0.f, 0.f);

    int i = 0;
    for (; i + 4 <= deg; i += 4) {
        int s0 = g_ssrc[off + i];
        int s1 = g_ssrc[off + i + 1];
        int s2 = g_ssrc[off + i + 2];
        int s3 = g_ssrc[off + i + 3];
        float4 k0 = *(const float4*)&g_QKVS1[s0 * 512 + 128 + lane * 4];
        float4 k1 = *(const float4*)&g_QKVS1[s1 * 512 + 128 + lane * 4];
        float4 k2 = *(const float4*)&g_QKVS1[s2 * 512 + 128 + lane * 4];
        float4 k3 = *(const float4*)&g_QKVS1[s3 * 512 + 128 + lane * 4];
        float4 v0 = *(const float4*)&g_QKVS1[s0 * 512 + 256 + lane * 4];
        float4 v1 = *(const float4*)&g_QKVS1[s1 * 512 + 256 + lane * 4];
        float4 v2 = *(const float4*)&g_QKVS1[s2 * 512 + 256 + lane * 4];
        float4 v3 = *(const float4*)&g_QKVS1[s3 * 512 + 256 + lane * 4];
        float p0 = dot4(q, k0), p1 = dot4(q, k1), p2 = dot4(q, k2), p3 = dot4(q, k3);
#pragma unroll
        for (int d = 4; d > 0; d >>= 1) {
            p0 += __shfl_xor_sync(0xffffffffu, p0, d, 8);
            p1 += __shfl_xor_sync(0xffffffffu, p1, d, 8);
            p2 += __shfl_xor_sync(0xffffffffu, p2, d, 8);
            p3 += __shfl_xor_sync(0xffffffffu, p3, d, 8);
        }
        float e0 = __expf(p0 * SCALE1);
        float e1 = __expf(p1 * SCALE1);
        float e2 = __expf(p2 * SCALE1);
        float e3 = __expf(p3 * SCALE1);
        sum += (e0 + e1) + (e2 + e3);
        acc.x += e0 * v0.x + e1 * v1.x + e2 * v2.x + e3 * v3.x;
        acc.y += e0 * v0.y + e1 * v1.y + e2 * v2.y + e3 * v3.y;
        acc.z += e0 * v0.z + e1 * v1.z + e2 * v2.z + e3 * v3.z;
        acc.w += e0 * v0.w + e1 * v1.w + e2 * v2.w + e3 * v3.w;
    }
    for (; i < deg; i++) {
        int s = g_ssrc[off + i];
        float4 k = *(const float4*)&g_QKVS1[s * 512 + 128 + lane * 4];
        float4 v = *(const float4*)&g_QKVS1[s * 512 + 256 + lane * 4];
        float p = dot4(q, k);
#pragma unroll
        for (int d = 4; d > 0; d >>= 1) p += __shfl_xor_sync(0xffffffffu, p, d, 8);
        float e = __expf(p * SCALE1);
        sum += e;
        acc.x += e * v.x; acc.y += e * v.y; acc.z += e * v.z; acc.w += e * v.w;
    }

    float inv = 1.0f / (sum + EPSV);
    float4 sk = *(const float4*)&g_QKVS1[n * 512 + 384 + lane * 4];
    float4 h1;
    h1.x = fmaxf(acc.x * inv + sk.x, 0.0f);
    h1.y = fmaxf(acc.y * inv + sk.y, 0.0f);
    h1.z = fmaxf(acc.z * inv + sk.z, 0.0f);
    h1.w = fmaxf(acc.w * inv + sk.w, 0.0f);

    // gemm2: 16 outputs per node, reduce across warp
    float part[16];
#pragma unroll
    for (int j = 0; j < 16; j++) {
        float4 w = *(float4*)&Wsm[j][lane * 4];
        part[j] = h1.x * w.x + h1.y * w.y + h1.z * w.z + h1.w * w.w;
#pragma unroll
        for (int s = 16; s > 0; s >>= 1)
            part[j] += __shfl_xor_sync(0xffffffffu, part[j], s);
    }
    if (lane == 0) {
        // layout: [q(4) | kv interleaved(8) | s(4)]
        float o[16];
#pragma unroll
        for (int c = 0; c < 4; c++) {
            o[c]          = part[c]      + bsm[c];        // q
            o[4 + 2 * c]  = part[4 + c]  + bsm[4 + c];    // k
            o[5 + 2 * c]  = part[8 + c]  + bsm[8 + c];    // v
            o[12 + c]     = part[12 + c] + bsm[12 + c];   // s
        }
#pragma unroll
        for (int j4 = 0; j4 < 4; j4++)
            *(float4*)&g_QKVS2[n * 16 + j4 * 4] = make_float4(o[j4*4], o[j4*4+1], o[j4*4+2], o[j4*4+3]);
    }
}

// ---------------- layer-2 edge phase + final linear + mean (one kernel) ---
// thread per (node, head); max-free softmax; last block writes output.
__global__ __launch_bounds__(256) void edge2_fused(
        const float* __restrict__ Wl, const float* __restrict__ bl,
        float* __restrict__ out) {
    __shared__ float ysm[8];
    int tid = threadIdx.x;
    int t = blockIdx.x * 256 + tid;
    int n = t >> 2, h = t & 3;

    float y = 0.0f;
    if (n < NN) {
        int off = g_off[n], end = g_off[n + 1];
        float qh = g_QKVS2[n * 16 + h];
        float s = 0.0f, a = 0.0f;
        int i = off;
        for (; i + 4 <= end; i += 4) {
            int s0 = g_ssrc[i], s1 = g_ssrc[i + 1], s2 = g_ssrc[i + 2], s3 = g_ssrc[i + 3];
            float2 kv0 = *(const float2*)&g_QKVS2[s0 * 16 + 4 + 2 * h];
            float2 kv1 = *(const float2*)&g_QKVS2[s1 * 16 + 4 + 2 * h];
            float2 kv2 = *(const float2*)&g_QKVS2[s2 * 16 + 4 + 2 * h];
            float2 kv3 = *(const float2*)&g_QKVS2[s3 * 16 + 4 + 2 * h];
            float e0 = __expf(qh * kv0.x);
            float e1 = __expf(qh * kv1.x);
            float e2 = __expf(qh * kv2.x);
            float e3 = __expf(qh * kv3.x);
            s += (e0 + e1) + (e2 + e3);
            a += e0 * kv0.y + e1 * kv1.y + e2 * kv2.y + e3 * kv3.y;
        }
        for (; i < end; i++) {
            int sn = g_ssrc[i];
            float2 kv = *(const float2*)&g_QKVS2[sn * 16 + 4 + 2 * h];
            float e = __expf(qh * kv.x);
            s += e;
            a += e * kv.y;
        }
        float o = a / (s + EPSV) + g_QKVS2[n * 16 + 12 + h];
        y = o * Wl[h];
    }

    // block reduction
#pragma unroll
    for (int d = 16; d > 0; d >>= 1) y += __shfl_xor_sync(0xffffffffu, y, d);
    if ((tid & 31) == 0) ysm[tid >> 5] = y;
    __syncthreads();
    if (tid == 0) {
        float tsum = 0.f;
#pragma unroll
        for (int w = 0; w < 8; w++) tsum += ysm[w];
        atomicAdd(&g_accum, tsum);
        __threadfence();
        int ticket = atomicAdd(&g_done, 1);
        if (ticket == (int)gridDim.x - 1) {
            out[0] = g_accum * (1.0f / (float)NN) + bl[0];
        }
    }
}

// ---------------- launch --------------------------------------------------
extern "C" void kernel_launch(void* const* d_in, const int* in_sizes, int n_in,
                              void* d_out, int out_size) {
    const float* x    = (const float*)d_in[0];
    const int*   esrc = (const int*)d_in[1];
    const int*   edst = (const int*)d_in[2];
    const float* W1q = (const float*)d_in[3];  const float* b1q = (const float*)d_in[4];
    const float* W1k = (const float*)d_in[5];  const float* b1k = (const float*)d_in[6];
    const float* W1v = (const float*)d_in[7];  const float* b1v = (const float*)d_in[8];
    const float* W1s = (const float*)d_in[9];  const float* b1s = (const float*)d_in[10];
    const float* W2q = (const float*)d_in[11]; const float* b2q = (const float*)d_in[12];
    const float* W2k = (const float*)d_in[13]; const float* b2k = (const float*)d_in[14];
    const float* W2v = (const float*)d_in[15]; const float* b2v = (const float*)d_in[16];
    const float* W2s = (const float*)d_in[17]; const float* b2s = (const float*)d_in[18];
    const float* Wl  = (const float*)d_in[19]; const float* bl  = (const float*)d_in[20];
    float* out = (float*)d_out;

    init_kernel<<<(NN + 255) / 256, 256>>>();
    hist_kernel<<<(EE / 4 + 255) / 256, 256>>>(edst);
    scan_kernel<<<1, 1024>>>();
    scatter_kernel<<<(EE / 4 + 255) / 256, 256>>>(esrc, edst);

    dim3 g1((NN + 127) / 128, 4);
    gemm1_kernel<<<g1, 256>>>(x, W1q, b1q, W1k, b1k, W1v, b1v, W1s, b1s);

    edge1_fused<<<NN / 8, 256>>>(W2q, b2q, W2k, b2k, W2v, b2v, W2s, b2s);
    edge2_fused<<<(NN * 4 + 255) / 256, 256>>>(Wl, bl, out);
}

// round 7
// speedup vs baseline: 1.4262x; 1.0576x over previous
#include <cuda_runtime.h>
#include <math.h>
#include <float.h>

#define NN 20000
#define EE 320000
#define EPSV 1e-16f
#define SCALE1 0.17677669529663687f   // 1/sqrt(32)

// ---------------- device scratch (static; no cudaMalloc) ------------------
__device__ float g_QKVS1[NN * 512];   // per node: [q(128)|k(128)|v(128)|s(128)]
__device__ float g_QKVS2[NN * 16];    // per node: [q(4)|kv interleaved(8)|s(4)]
__device__ int   g_deg[NN];
__device__ int   g_off[NN + 1];
__device__ int   g_pos[NN];
__device__ int   g_ssrc[EE];          // src sorted by dst (CSR payload)
__device__ float g_accum;
__device__ int   g_done;

// ---------------- f32x2 packed-FMA helpers --------------------------------
#define FMA2(d, a, b, c) \
    asm("fma.rn.f32x2 %0, %1, %2, %3;" : "=l"(d) : "l"(a), "l"(b), "l"(c))

__device__ __forceinline__ unsigned long long pack2(float lo, float hi) {
    unsigned long long o;
    asm("mov.b64 %0, {%1, %2};" : "=l"(o) : "r"(__float_as_uint(lo)), "r"(__float_as_uint(hi)));
    return o;
}
__device__ __forceinline__ float2 unpack2(unsigned long long v) {
    unsigned lo, hi;
    asm("mov.b64 {%0, %1}, %2;" : "=r"(lo), "=r"(hi) : "l"(v));
    return make_float2(__uint_as_float(lo), __uint_as_float(hi));
}
__device__ __forceinline__ float dot4(float4 a, float4 b) {
    return a.x * b.x + a.y * b.y + a.z * b.z + a.w * b.w;
}

// ---------------- init ----------------------------------------------------
__global__ void init_kernel() {
    int i = blockIdx.x * blockDim.x + threadIdx.x;
    if (i < NN) g_deg[i] = 0;
    if (i == 0) { g_accum = 0.0f; g_done = 0; }
}

// ---------------- CSR build (4 edges/thread for MLP) ----------------------
__global__ void hist_kernel(const int* __restrict__ dst) {
    int t = blockIdx.x * blockDim.x + threadIdx.x;
    int e = t * 4;
    if (e < EE) {
        int4 d4 = *(const int4*)&dst[e];
        atomicAdd(&g_deg[d4.x], 1);
        atomicAdd(&g_deg[d4.y], 1);
        atomicAdd(&g_deg[d4.z], 1);
        atomicAdd(&g_deg[d4.w], 1);
    }
}

// single-block exclusive scan over g_deg -> g_off, g_pos
__global__ void scan_kernel() {
    __shared__ int wsum[32];
    __shared__ int carry_sh;
    int tid = threadIdx.x;
    int lane = tid & 31, wid = tid >> 5;
    if (tid == 0) { carry_sh = 0; g_off[0] = 0; }
    __syncthreads();

    const int CHUNKS = (NN + 1023) / 1024;
    for (int c = 0; c < CHUNKS; c++) {
        int i = c * 1024 + tid;
        int v = (i < NN) ? g_deg[i] : 0;
        int base = carry_sh;
        int incl = v;
#pragma unroll
        for (int d = 1; d < 32; d <<= 1) {
            int t = __shfl_up_sync(0xffffffffu, incl, d);
            if (lane >= d) incl += t;
        }
        if (lane == 31) wsum[wid] = incl;
        __syncthreads();
        if (wid == 0) {
            int wi = wsum[lane];
#pragma unroll
            for (int d = 1; d < 32; d <<= 1) {
                int t = __shfl_up_sync(0xffffffffu, wi, d);
                if (lane >= d) wi += t;
            }
            wsum[lane] = wi;
        }
        __syncthreads();
        int wexcl = (wid == 0) ? 0 : wsum[wid - 1];
        int total = wsum[31];
        int my_incl = base + wexcl + incl;
        if (i < NN) {
            g_off[i + 1] = my_incl;
            g_pos[i] = my_incl - v;
        }
        __syncthreads();
        if (tid == 0) carry_sh = base + total;
        __syncthreads();
    }
}

__global__ void scatter_kernel(const int* __restrict__ src, const int* __restrict__ dst) {
    int t = blockIdx.x * blockDim.x + threadIdx.x;
    int e = t * 4;
    if (e >= EE) return;
    int4 d4 = *(const int4*)&dst[e];
    int4 s4 = *(const int4*)&src[e];
    int p0 = atomicAdd(&g_pos[d4.x], 1);
    int p1 = atomicAdd(&g_pos[d4.y], 1);
    int p2 = atomicAdd(&g_pos[d4.z], 1);
    int p3 = atomicAdd(&g_pos[d4.w], 1);
    g_ssrc[p0] = s4.x;
    g_ssrc[p1] = s4.y;
    g_ssrc[p2] = s4.z;
    g_ssrc[p3] = s4.w;
}

// ---------------- layer-1 fused QKVS GEMM (f32x2, MOV-free inner loop) ----
__global__ __launch_bounds__(256) void gemm1_kernel(
        const float* __restrict__ x,
        const float* __restrict__ Wq, const float* __restrict__ bq,
        const float* __restrict__ Wk, const float* __restrict__ bk,
        const float* __restrict__ Wv, const float* __restrict__ bv,
        const float* __restrict__ Ws, const float* __restrict__ bs) {
    __shared__ unsigned long long As2[16][128];   // (a,a) packed, [k][row]
    __shared__ float Bs[16][128];                 // [k][col]

    int tid = threadIdx.x;
    int tx = tid & 15;
    int ty = tid >> 4;
    int row0 = blockIdx.x * 128;
    int m = blockIdx.y;

    const float* W = (m == 0) ? Wq : (m == 1) ? Wk : (m == 2) ? Wv : Ws;
    const float* B = (m == 0) ? bq : (m == 1) ? bk : (m == 2) ? bv : bs;

    unsigned long long acc[8][4];
#pragma unroll
    for (int i = 0; i < 8; i++)
#pragma unroll
        for (int j = 0; j < 4; j++) acc[i][j] = 0ull;

    int arow = tid & 127;
    int akq  = (tid >> 7) * 8;
    int bcol = (tid & 31) * 4;
    int bkr  = tid >> 5;

    for (int kt = 0; kt < 8; kt++) {
        int k0 = kt * 16;
        int gr = row0 + arow;
        float4 xa = make_float4(0.f, 0.f, 0.f, 0.f);
        float4 xb = make_float4(0.f, 0.f, 0.f, 0.f);
        if (gr < NN) {
            xa = *(const float4*)&x[gr * 128 + k0 + akq];
            xb = *(const float4*)&x[gr * 128 + k0 + akq + 4];
        }
        As2[akq + 0][arow] = pack2(xa.x, xa.x);
        As2[akq + 1][arow] = pack2(xa.y, xa.y);
        As2[akq + 2][arow] = pack2(xa.z, xa.z);
        As2[akq + 3][arow] = pack2(xa.w, xa.w);
        As2[akq + 4][arow] = pack2(xb.x, xb.x);
        As2[akq + 5][arow] = pack2(xb.y, xb.y);
        As2[akq + 6][arow] = pack2(xb.z, xb.z);
        As2[akq + 7][arow] = pack2(xb.w, xb.w);
        *(float4*)&Bs[bkr][bcol]     = *(const float4*)&W[(k0 + bkr) * 128 + bcol];
        *(float4*)&Bs[bkr + 8][bcol] = *(const float4*)&W[(k0 + bkr + 8) * 128 + bcol];
        __syncthreads();

#pragma unroll
        for (int kk = 0; kk < 16; kk++) {
            ulonglong2 b01 = *(ulonglong2*)&Bs[kk][tx * 8];
            ulonglong2 b23 = *(ulonglong2*)&Bs[kk][tx * 8 + 4];
#pragma unroll
            for (int i = 0; i < 8; i++) {
                unsigned long long a = As2[kk][ty * 8 + i];
                FMA2(acc[i][0], a, b01.x, acc[i][0]);
                FMA2(acc[i][1], a, b01.y, acc[i][1]);
                FMA2(acc[i][2], a, b23.x, acc[i][2]);
                FMA2(acc[i][3], a, b23.y, acc[i][3]);
            }
        }
        __syncthreads();
    }

    float4 bb0 = *(const float4*)&B[tx * 8];
    float4 bb1 = *(const float4*)&B[tx * 8 + 4];
#pragma unroll
    for (int i = 0; i < 8; i++) {
        int gr = row0 + ty * 8 + i;
        if (gr < NN) {
            float2 p0 = unpack2(acc[i][0]);
            float2 p1 = unpack2(acc[i][1]);
            float2 p2 = unpack2(acc[i][2]);
            float2 p3 = unpack2(acc[i][3]);
            float4 o0 = make_float4(p0.x + bb0.x, p0.y + bb0.y, p1.x + bb0.z, p1.y + bb0.w);
            float4 o1 = make_float4(p2.x + bb1.x, p2.y + bb1.y, p3.x + bb1.z, p3.y + bb1.w);
            *(float4*)&g_QKVS1[gr * 512 + m * 128 + tx * 8]     = o0;
            *(float4*)&g_QKVS1[gr * 512 + m * 128 + tx * 8 + 4] = o1;
        }
    }
}

// ---------------- layer-1 fused edge phase + gemm2 (single pass) ----------
// warp per dst node; 16 lanes per edge (2 edges in flight per warp);
// LOCKSTEP loop: both halves run ceil(deg/2) predicated iterations so every
// __shfl_xor_sync executes fully converged.
__global__ __launch_bounds__(256) void edge1_fused(
        const float* __restrict__ W2q, const float* __restrict__ b2q,
        const float* __restrict__ W2k, const float* __restrict__ b2k,
        const float* __restrict__ W2v, const float* __restrict__ b2v,
        const float* __restrict__ W2s, const float* __restrict__ b2s) {
    __shared__ float Wsm[16][128];    // [out j][in i], j = m*4+c
    __shared__ float bsm[16];

    int tid = threadIdx.x;
    for (int f = tid; f < 2048; f += 256) {
        int j = f >> 7, i = f & 127;
        int mm = j >> 2, c = j & 3;
        const float* Wm = (mm == 0) ? W2q : (mm == 1) ? W2k : (mm == 2) ? W2v : W2s;
        Wsm[j][i] = Wm[i * 4 + c];
    }
    if (tid < 16) {
        int mm = tid >> 2, c = tid & 3;
        const float* bm = (mm == 0) ? b2q : (mm == 1) ? b2k : (mm == 2) ? b2v : b2s;
        bsm[tid] = bm[c];
    }
    __syncthreads();

    int wid = tid >> 5, lane = tid & 31;
    int half = lane >> 4;          // 0/1: edge parity
    int l = lane & 15;             // channel group: floats [8l, 8l+8)
    int n = blockIdx.x * 8 + wid;  // 2500*8 = 20000 exactly

    int off = g_off[n], end = g_off[n + 1];
    int deg = end - off;
    int steps = (deg + 1) >> 1;    // identical for both halves

    const float* base1 = &g_QKVS1[(size_t)n * 512 + l * 8];
    float4 qa = *(const float4*)(base1);
    float4 qb = *(const float4*)(base1 + 4);

    float se = 0.0f;
    float4 aca = make_float4(0.f, 0.f, 0.f, 0.f);
    float4 acb = make_float4(0.f, 0.f, 0.f, 0.f);

    int j = 0;
    for (; j + 2 <= steps; j += 2) {
        int i0 = 2 * j + half;
        int i1 = i0 + 2;
        bool ok0 = i0 < deg;
        bool ok1 = i1 < deg;
        int s0 = g_ssrc[off + (ok0 ? i0 : 0)];
        int s1 = g_ssrc[off + (ok1 ? i1 : 0)];
        const float* p0 = &g_QKVS1[(size_t)s0 * 512 + 128 + l * 8];
        const float* p1 = &g_QKVS1[(size_t)s1 * 512 + 128 + l * 8];
        float4 k0a = *(const float4*)(p0);
        float4 k0b = *(const float4*)(p0 + 4);
        float4 k1a = *(const float4*)(p1);
        float4 k1b = *(const float4*)(p1 + 4);
        float4 v0a = *(const float4*)(p0 + 128);
        float4 v0b = *(const float4*)(p0 + 132);
        float4 v1a = *(const float4*)(p1 + 128);
        float4 v1b = *(const float4*)(p1 + 132);
        float d0 = dot4(qa, k0a) + dot4(qb, k0b);
        float d1 = dot4(qa, k1a) + dot4(qb, k1b);
        d0 += __shfl_xor_sync(0xffffffffu, d0, 1, 4);
        d1 += __shfl_xor_sync(0xffffffffu, d1, 1, 4);
        d0 += __shfl_xor_sync(0xffffffffu, d0, 2, 4);
        d1 += __shfl_xor_sync(0xffffffffu, d1, 2, 4);
        float e0 = ok0 ? __expf(d0 * SCALE1) : 0.0f;
        float e1 = ok1 ? __expf(d1 * SCALE1) : 0.0f;
        se += e0 + e1;
        aca.x += e0 * v0a.x + e1 * v1a.x;
        aca.y += e0 * v0a.y + e1 * v1a.y;
        aca.z += e0 * v0a.z + e1 * v1a.z;
        aca.w += e0 * v0a.w + e1 * v1a.w;
        acb.x += e0 * v0b.x + e1 * v1b.x;
        acb.y += e0 * v0b.y + e1 * v1b.y;
        acb.z += e0 * v0b.z + e1 * v1b.z;
        acb.w += e0 * v0b.w + e1 * v1b.w;
    }
    if (j < steps) {
        int i0 = 2 * j + half;
        bool ok0 = i0 < deg;
        int s = g_ssrc[off + (ok0 ? i0 : 0)];
        const float* p = &g_QKVS1[(size_t)s * 512 + 128 + l * 8];
        float4 ka = *(const float4*)(p);
        float4 kb = *(const float4*)(p + 4);
        float4 va = *(const float4*)(p + 128);
        float4 vb = *(const float4*)(p + 132);
        float d = dot4(qa, ka) + dot4(qb, kb);
        d += __shfl_xor_sync(0xffffffffu, d, 1, 4);
        d += __shfl_xor_sync(0xffffffffu, d, 2, 4);
        float e = ok0 ? __expf(d * SCALE1) : 0.0f;
        se += e;
        aca.x += e * va.x; aca.y += e * va.y; aca.z += e * va.z; aca.w += e * va.w;
        acb.x += e * vb.x; acb.y += e * vb.y; acb.z += e * vb.z; acb.w += e * vb.w;
    }

    // cross-half combine (halves processed disjoint edge sets)
    se += __shfl_xor_sync(0xffffffffu, se, 16);
    aca.x += __shfl_xor_sync(0xffffffffu, aca.x, 16);
    aca.y += __shfl_xor_sync(0xffffffffu, aca.y, 16);
    aca.z += __shfl_xor_sync(0xffffffffu, aca.z, 16);
    aca.w += __shfl_xor_sync(0xffffffffu, aca.w, 16);
    acb.x += __shfl_xor_sync(0xffffffffu, acb.x, 16);
    acb.y += __shfl_xor_sync(0xffffffffu, acb.y, 16);
    acb.z += __shfl_xor_sync(0xffffffffu, acb.z, 16);
    acb.w += __shfl_xor_sync(0xffffffffu, acb.w, 16);

    float inv = 1.0f / (se + EPSV);
    float4 ska = *(const float4*)(base1 + 384);
    float4 skb = *(const float4*)(base1 + 388);
    float4 h1a, h1b;
    h1a.x = fmaxf(aca.x * inv + ska.x, 0.0f);
    h1a.y = fmaxf(aca.y * inv + ska.y, 0.0f);
    h1a.z = fmaxf(aca.z * inv + ska.z, 0.0f);
    h1a.w = fmaxf(aca.w * inv + ska.w, 0.0f);
    h1b.x = fmaxf(acb.x * inv + skb.x, 0.0f);
    h1b.y = fmaxf(acb.y * inv + skb.y, 0.0f);
    h1b.z = fmaxf(acb.z * inv + skb.z, 0.0f);
    h1b.w = fmaxf(acb.w * inv + skb.w, 0.0f);

    // gemm2: half0 computes outputs j=0..7, half1 computes j=8..15
    int jbase = half * 8;
    float part[8];
#pragma unroll
    for (int jj = 0; jj < 8; jj++) {
        int jo = jbase + jj;
        float4 w0 = *(float4*)&Wsm[jo][l * 8];
        float4 w1 = *(float4*)&Wsm[jo][l * 8 + 4];
        float p = dot4(h1a, w0) + dot4(h1b, w1);
#pragma unroll
        for (int d = 8; d > 0; d >>= 1)
            p += __shfl_xor_sync(0xffffffffu, p, d, 16);
        part[jj] = p;
    }
    if (l == 0) {
        // output layout: [q(4) | kv interleaved(8) | s(4)]
        float* o = &g_QKVS2[n * 16];
        if (half == 0) {
#pragma unroll
            for (int c = 0; c < 4; c++) {
                o[c] = part[c] + bsm[c];                    // q
                o[4 + 2 * c] = part[4 + c] + bsm[4 + c];    // k
            }
        } else {
#pragma unroll
            for (int c = 0; c < 4; c++) {
                o[5 + 2 * c] = part[c] + bsm[8 + c];        // v
                o[12 + c]    = part[4 + c] + bsm[12 + c];   // s
            }
        }
    }
}

// ---------------- layer-2 edge phase + final linear + mean (one kernel) ---
__global__ __launch_bounds__(256) void edge2_fused(
        const float* __restrict__ Wl, const float* __restrict__ bl,
        float* __restrict__ out) {
    __shared__ float ysm[8];
    int tid = threadIdx.x;
    int t = blockIdx.x * 256 + tid;
    int n = t >> 2, h = t & 3;

    float y = 0.0f;
    if (n < NN) {
        int off = g_off[n], end = g_off[n + 1];
        float qh = g_QKVS2[n * 16 + h];
        float s = 0.0f, a = 0.0f;
        int i = off;
        for (; i + 4 <= end; i += 4) {
            int s0 = g_ssrc[i], s1 = g_ssrc[i + 1], s2 = g_ssrc[i + 2], s3 = g_ssrc[i + 3];
            float2 kv0 = *(const float2*)&g_QKVS2[s0 * 16 + 4 + 2 * h];
            float2 kv1 = *(const float2*)&g_QKVS2[s1 * 16 + 4 + 2 * h];
            float2 kv2 = *(const float2*)&g_QKVS2[s2 * 16 + 4 + 2 * h];
            float2 kv3 = *(const float2*)&g_QKVS2[s3 * 16 + 4 + 2 * h];
            float e0 = __expf(qh * kv0.x);
            float e1 = __expf(qh * kv1.x);
            float e2 = __expf(qh * kv2.x);
            float e3 = __expf(qh * kv3.x);
            s += (e0 + e1) + (e2 + e3);
            a += e0 * kv0.y + e1 * kv1.y + e2 * kv2.y + e3 * kv3.y;
        }
        for (; i < end; i++) {
            int sn = g_ssrc[i];
            float2 kv = *(const float2*)&g_QKVS2[sn * 16 + 4 + 2 * h];
            float e = __expf(qh * kv.x);
            s += e;
            a += e * kv.y;
        }
        float o = a / (s + EPSV) + g_QKVS2[n * 16 + 12 + h];
        y = o * Wl[h];
    }

#pragma unroll
    for (int d = 16; d > 0; d >>= 1) y += __shfl_xor_sync(0xffffffffu, y, d);
    if ((tid & 31) == 0) ysm[tid >> 5] = y;
    __syncthreads();
    if (tid == 0) {
        float tsum = 0.f;
#pragma unroll
        for (int w = 0; w < 8; w++) tsum += ysm[w];
        atomicAdd(&g_accum, tsum);
        __threadfence();
        int ticket = atomicAdd(&g_done, 1);
        if (ticket == (int)gridDim.x - 1) {
            out[0] = g_accum * (1.0f / (float)NN) + bl[0];
        }
    }
}

// ---------------- launch --------------------------------------------------
extern "C" void kernel_launch(void* const* d_in, const int* in_sizes, int n_in,
                              void* d_out, int out_size) {
    const float* x    = (const float*)d_in[0];
    const int*   esrc = (const int*)d_in[1];
    const int*   edst = (const int*)d_in[2];
    const float* W1q = (const float*)d_in[3];  const float* b1q = (const float*)d_in[4];
    const float* W1k = (const float*)d_in[5];  const float* b1k = (const float*)d_in[6];
    const float* W1v = (const float*)d_in[7];  const float* b1v = (const float*)d_in[8];
    const float* W1s = (const float*)d_in[9];  const float* b1s = (const float*)d_in[10];
    const float* W2q = (const float*)d_in[11]; const float* b2q = (const float*)d_in[12];
    const float* W2k = (const float*)d_in[13]; const float* b2k = (const float*)d_in[14];
    const float* W2v = (const float*)d_in[15]; const float* b2v = (const float*)d_in[16];
    const float* W2s = (const float*)d_in[17]; const float* b2s = (const float*)d_in[18];
    const float* Wl  = (const float*)d_in[19]; const float* bl  = (const float*)d_in[20];
    float* out = (float*)d_out;

    // one-time creation of side stream + events (not device memory)
    static cudaStream_t sB = nullptr;
    static cudaEvent_t evFork = nullptr, evJoin = nullptr;
    if (!sB) {
        cudaStreamCreateWithFlags(&sB, cudaStreamNonBlocking);
        cudaEventCreateWithFlags(&evFork, cudaEventDisableTiming);
        cudaEventCreateWithFlags(&evJoin, cudaEventDisableTiming);
    }

    // fork: CSR build on sB, overlapped with gemm1 on the main stream
    cudaEventRecord(evFork, 0);
    cudaStreamWaitEvent(sB, evFork, 0);

    init_kernel<<<(NN + 255) / 256, 256, 0, sB>>>();
    hist_kernel<<<(EE / 4 + 255) / 256, 256, 0, sB>>>(edst);
    scan_kernel<<<1, 1024, 0, sB>>>();
    scatter_kernel<<<(EE / 4 + 255) / 256, 256, 0, sB>>>(esrc, edst);
    cudaEventRecord(evJoin, sB);

    dim3 g1((NN + 127) / 128, 4);
    gemm1_kernel<<<g1, 256>>>(x, W1q, b1q, W1k, b1k, W1v, b1v, W1s, b1s);

    // join: edge phase needs both gemm1 (main) and CSR (sB)
    cudaStreamWaitEvent(0, evJoin, 0);

    edge1_fused<<<NN / 8, 256>>>(W2q, b2q, W2k, b2k, W2v, b2v, W2s, b2s);
    edge2_fused<<<(NN * 4 + 255) / 256, 256>>>(Wl, bl, out);
}